// round 4
// baseline (speedup 1.0000x reference)
#include <cuda_runtime.h>
#include <cstdint>

#define NCTA 128
#define NTHR 256
#define SLOT 4096                       // float2 entries per weight slot (256 kp x 16 cols)
#define SMEM_BYTES (4*SLOT*8 + 1024)    // 4 slots + bias/misc region

// ---------------- persistent device state (no allocations allowed) ----------
__device__ float2 g_h0[2][32768];            // layer0 h, transposed [256 kp][128 b], parity
__device__ float2 g_h1[2][32768];            // layer1 h
__device__ float  g_arch[256][512*128];      // decoder dh1 archive [t][k][b]
__device__ volatile unsigned g_gen;
__device__ unsigned g_cnt;

// ---------------- grid barrier (all 128 CTAs co-resident) -------------------
__device__ __forceinline__ void grid_sync() {
    __syncthreads();
    __threadfence();
    if (threadIdx.x == 0) {
        unsigned gen = g_gen;
        if (atomicAdd(&g_cnt, 1u) == NCTA - 1u) {
            atomicExch(&g_cnt, 0u);
            __threadfence();
            g_gen = gen + 1u;
        } else {
            while (g_gen == gen) __nanosleep(64);
        }
    }
    __syncthreads();
}

// ---------------- packed fp32x2 FMA (Blackwell FFMA2) -----------------------
__device__ __forceinline__ unsigned long long ffma2(unsigned long long a,
                                                    unsigned long long b,
                                                    unsigned long long c) {
    unsigned long long d;
    asm("fma.rn.f32x2 %0, %1, %2, %3;" : "=l"(d) : "l"(a), "l"(b), "l"(c));
    return d;
}
__device__ __forceinline__ float upsum(unsigned long long a) {
    return __uint_as_float((unsigned)a) + __uint_as_float((unsigned)(a >> 32));
}

// ---------------- GEMM over one 512-k matrix slice --------------------------
// w: smem slot [256 kp][16 cols] float2 ; h: global transposed [256 kp][128 b]
__device__ __forceinline__ void mm512(const float2* __restrict__ w,
                                      const unsigned long long* __restrict__ h,
                                      int b, int ug, unsigned long long acc[8]) {
    const unsigned long long* hp = h + b;
    const char* wb = (const char*)(w + ug * 8);   // 128B stride per kp row
    unsigned long long hv[8];
#pragma unroll
    for (int j = 0; j < 8; j++) hv[j] = __ldcg(hp + j * 128);
    for (int kp0 = 0; kp0 < 256; kp0 += 8) {
        unsigned long long hn[8];
        if (kp0 + 8 < 256) {
#pragma unroll
            for (int j = 0; j < 8; j++) hn[j] = __ldcg(hp + (kp0 + 8 + j) * 128);
        }
#pragma unroll
        for (int j = 0; j < 8; j++) {
            const ulonglong2* wr = (const ulonglong2*)(wb + (size_t)(kp0 + j) * 128);
            ulonglong2 a0 = wr[0], a1 = wr[1], a2 = wr[2], a3 = wr[3];
            acc[0] = ffma2(a0.x, hv[j], acc[0]);
            acc[1] = ffma2(a0.y, hv[j], acc[1]);
            acc[2] = ffma2(a1.x, hv[j], acc[2]);
            acc[3] = ffma2(a1.y, hv[j], acc[3]);
            acc[4] = ffma2(a2.x, hv[j], acc[4]);
            acc[5] = ffma2(a2.y, hv[j], acc[5]);
            acc[6] = ffma2(a3.x, hv[j], acc[6]);
            acc[7] = ffma2(a3.y, hv[j], acc[7]);
        }
#pragma unroll
        for (int j = 0; j < 8; j++) hv[j] = hn[j];
    }
}

// ---------------- LSTM cell update (2 units per thread) ---------------------
__device__ __forceinline__ void cell2(const float s[8], const float* __restrict__ bias,
                                      int ug, int b, int ubase, float cr[2],
                                      float* __restrict__ hdst, float* __restrict__ arch) {
#pragma unroll
    for (int u = 0; u < 2; u++) {
        int col = ug * 8 + u * 4;
        float gi = s[u * 4 + 0] + bias[col + 0];
        float gf = s[u * 4 + 1] + bias[col + 1];
        float gg = s[u * 4 + 2] + bias[col + 2];
        float go = s[u * 4 + 3] + bias[col + 3];
        float iv = 1.f / (1.f + expf(-gi));
        float fv = 1.f / (1.f + expf(-gf));
        float gv = tanhf(gg);
        float ov = 1.f / (1.f + expf(-go));
        float c  = fv * cr[u] + iv * gv;
        cr[u] = c;
        float hv = ov * tanhf(c);
        int j = ubase + ug * 2 + u;
        __stcg(hdst + (j >> 1) * 256 + b * 2 + (j & 1), hv);
        if (arch) __stcg(arch + j * 128 + b, hv);
    }
}

// Pack a (2048 x 512) weight matrix's 16 rows for this CTA into a slot.
__device__ void pack_slot(const float* __restrict__ W, float2* __restrict__ dst, int cta) {
    for (int i = threadIdx.x; i < SLOT; i += NTHR) {
        int col = i & 15, kp = i >> 4;
        int r = (col & 3) * 512 + cta * 4 + (col >> 2);
        dst[kp * 16 + col] = *(const float2*)(W + (size_t)r * 512 + kp * 2);
    }
}

// ============================================================================
__global__ void __launch_bounds__(NTHR, 1)
seq2seq_kernel(const float* __restrict__ src,
               const float* __restrict__ eWih0, const float* __restrict__ eWhh0,
               const float* __restrict__ ebih0, const float* __restrict__ ebhh0,
               const float* __restrict__ eWih1, const float* __restrict__ eWhh1,
               const float* __restrict__ ebih1, const float* __restrict__ ebhh1,
               const float* __restrict__ dWih0, const float* __restrict__ dWhh0,
               const float* __restrict__ dbih0, const float* __restrict__ dbhh0,
               const float* __restrict__ dWih1, const float* __restrict__ dWhh1,
               const float* __restrict__ dbih1, const float* __restrict__ dbhh1,
               const float* __restrict__ fcW,  const float* __restrict__ fcb,
               float* __restrict__ out) {
    extern __shared__ char smem[];
    float2* slot0 = (float2*)smem;
    float2* slot1 = slot0 + SLOT;
    float2* slot2 = slot1 + SLOT;
    float2* slot3 = slot2 + SLOT;
    float*  sb    = (float*)(slot3 + SLOT);  // [0..15] b0, [16..31] b1, [32..47] bfold, [48..143] wx

    int tid = threadIdx.x, cta = blockIdx.x;
    int b = tid & 127, ug = tid >> 7;
    int ubase = cta * 4;

    // zero parity h buffers
    {
        float2 z = make_float2(0.f, 0.f);
        int gid = cta * NTHR + tid;
        for (int i = gid; i < 65536; i += NCTA * NTHR) {
            (&g_h0[0][0])[i] = z;
            (&g_h1[0][0])[i] = z;
        }
    }
    // pack encoder weights
    pack_slot(eWhh0, slot0, cta);
    pack_slot(eWih1, slot1, cta);
    pack_slot(eWhh1, slot2, cta);
    if (tid < 16) {
        int r = (tid & 3) * 512 + cta * 4 + (tid >> 2);
        sb[tid]      = ebih0[r] + ebhh0[r];
        sb[16 + tid] = ebih1[r] + ebhh1[r];
    }
    if (tid < 96) {
        int col = tid / 6, d = tid % 6;
        int r = (col & 3) * 512 + cta * 4 + (col >> 2);
        sb[48 + tid] = eWih0[r * 6 + d];
    }
    __syncthreads();
    grid_sync();

    float cr0[2] = {0.f, 0.f}, cr1[2] = {0.f, 0.f};
    int p = 0;

    // ---------------- encoder: 256 steps, 2 layers --------------------------
    for (int t = 0; t < 256; t++) {
        unsigned long long acc[8] = {0, 0, 0, 0, 0, 0, 0, 0};
        mm512(slot0, (const unsigned long long*)g_h0[p], b, ug, acc);
        float s[8];
#pragma unroll
        for (int i = 0; i < 8; i++) s[i] = upsum(acc[i]);
        {   // input term Wih0 @ x_t (6-dim)
            const float* xr = src + (size_t)b * 1536 + t * 6;
            float x0 = __ldg(xr), x1 = __ldg(xr + 1), x2 = __ldg(xr + 2);
            float x3 = __ldg(xr + 3), x4 = __ldg(xr + 4), x5 = __ldg(xr + 5);
#pragma unroll
            for (int i = 0; i < 8; i++) {
                const float* wr = sb + 48 + (ug * 8 + i) * 6;
                s[i] += wr[0]*x0 + wr[1]*x1 + wr[2]*x2 + wr[3]*x3 + wr[4]*x4 + wr[5]*x5;
            }
        }
        cell2(s, sb, ug, b, ubase, cr0, (float*)g_h0[p ^ 1], nullptr);
        grid_sync();
#pragma unroll
        for (int i = 0; i < 8; i++) acc[i] = 0;
        mm512(slot1, (const unsigned long long*)g_h0[p ^ 1], b, ug, acc);
        mm512(slot2, (const unsigned long long*)g_h1[p],     b, ug, acc);
#pragma unroll
        for (int i = 0; i < 8; i++) s[i] = upsum(acc[i]);
        cell2(s, sb + 16, ug, b, ubase, cr1, (float*)g_h1[p ^ 1], nullptr);
        grid_sync();
        p ^= 1;
    }

    // ---------------- repack decoder weights (SMEM-local) -------------------
    pack_slot(dWhh0, slot0, cta);
    pack_slot(dWih1, slot2, cta);
    pack_slot(dWhh1, slot3, cta);
    for (int i = tid; i < SLOT; i += NTHR) {   // Wfold = dWih0 @ fcW into slot1
        int col = i & 15, kp = i >> 4;
        int r = (col & 3) * 512 + cta * 4 + (col >> 2);
        float w0 = dWih0[r*6], w1 = dWih0[r*6+1], w2 = dWih0[r*6+2];
        float w3 = dWih0[r*6+3], w4 = dWih0[r*6+4], w5 = dWih0[r*6+5];
        float2 v; int k = kp * 2;
        v.x = w0*fcW[k] + w1*fcW[512+k] + w2*fcW[1024+k] + w3*fcW[1536+k] + w4*fcW[2048+k] + w5*fcW[2560+k];
        k++;
        v.y = w0*fcW[k] + w1*fcW[512+k] + w2*fcW[1024+k] + w3*fcW[1536+k] + w4*fcW[2048+k] + w5*fcW[2560+k];
        slot1[kp * 16 + col] = v;
    }
    if (tid < 16) {
        int r = (tid & 3) * 512 + cta * 4 + (tid >> 2);
        sb[tid]      = dbih0[r] + dbhh0[r];
        sb[16 + tid] = dbih1[r] + dbhh1[r];
        float bf = 0.f;
        for (int d = 0; d < 6; d++) bf += dWih0[r * 6 + d] * fcb[d];
        sb[32 + tid] = bf;
    }
    if (tid < 96) {
        int col = tid / 6, d = tid % 6;
        int r = (col & 3) * 512 + cta * 4 + (col >> 2);
        sb[48 + tid] = dWih0[r * 6 + d];
    }
    __syncthreads();

    // ---------------- decoder: 256 autoregressive steps ---------------------
    for (int t = 0; t < 256; t++) {
        unsigned long long acc[8] = {0, 0, 0, 0, 0, 0, 0, 0};
        mm512(slot0, (const unsigned long long*)g_h0[p], b, ug, acc);       // Whh0 @ dh0
        if (t > 0)
            mm512(slot1, (const unsigned long long*)g_h1[p], b, ug, acc);   // Wfold @ dh1
        float s[8];
#pragma unroll
        for (int i = 0; i < 8; i++) s[i] = upsum(acc[i]);
        if (t == 0) {   // inp_0 = src[:, -1, :]
            const float* xr = src + (size_t)b * 1536 + 255 * 6;
            float x0 = __ldg(xr), x1 = __ldg(xr + 1), x2 = __ldg(xr + 2);
            float x3 = __ldg(xr + 3), x4 = __ldg(xr + 4), x5 = __ldg(xr + 5);
#pragma unroll
            for (int i = 0; i < 8; i++) {
                const float* wr = sb + 48 + (ug * 8 + i) * 6;
                s[i] += wr[0]*x0 + wr[1]*x1 + wr[2]*x2 + wr[3]*x3 + wr[4]*x4 + wr[5]*x5;
            }
        } else {
#pragma unroll
            for (int i = 0; i < 8; i++) s[i] += sb[32 + ug * 8 + i];  // folded fc_b term
        }
        cell2(s, sb, ug, b, ubase, cr0, (float*)g_h0[p ^ 1], nullptr);
        grid_sync();
#pragma unroll
        for (int i = 0; i < 8; i++) acc[i] = 0;
        mm512(slot2, (const unsigned long long*)g_h0[p ^ 1], b, ug, acc);   // Wih1 @ dh0_new
        mm512(slot3, (const unsigned long long*)g_h1[p],     b, ug, acc);   // Whh1 @ dh1
#pragma unroll
        for (int i = 0; i < 8; i++) s[i] = upsum(acc[i]);
        cell2(s, sb + 16, ug, b, ubase, cr1, (float*)g_h1[p ^ 1], g_arch[t]);
        grid_sync();
        p ^= 1;
    }

    // ---------------- final FC over archived dh1 states ---------------------
    __syncthreads();
    float* fw = (float*)smem;   // reuse: fc_W (6 x 512) = 3072 floats
    for (int i = tid; i < 3072; i += NTHR) fw[i] = fcW[i];
    __syncthreads();
    {
        int tt = cta * 2 + (tid >> 7);
        int bb = tid & 127;
        const float* dp = g_arch[tt];
        float a0 = 0, a1 = 0, a2 = 0, a3 = 0, a4 = 0, a5 = 0;
        for (int k = 0; k < 512; k++) {
            float hv = __ldcg(dp + k * 128 + bb);
            a0 += fw[k] * hv;        a1 += fw[512 + k] * hv;  a2 += fw[1024 + k] * hv;
            a3 += fw[1536 + k] * hv; a4 += fw[2048 + k] * hv; a5 += fw[2560 + k] * hv;
        }
        float* op = out + (size_t)bb * 1536 + tt * 6;
        op[0] = a0 + __ldg(fcb);     op[1] = a1 + __ldg(fcb + 1);
        op[2] = a2 + __ldg(fcb + 2); op[3] = a3 + __ldg(fcb + 3);
        op[4] = a4 + __ldg(fcb + 4); op[5] = a5 + __ldg(fcb + 5);
    }
}

extern "C" void kernel_launch(void* const* d_in, const int* in_sizes, int n_in,
                              void* d_out, int out_size) {
    (void)in_sizes; (void)n_in; (void)out_size;
    cudaFuncSetAttribute(seq2seq_kernel,
                         cudaFuncAttributeMaxDynamicSharedMemorySize, SMEM_BYTES);
    const float* const* in = (const float* const*)d_in;
    seq2seq_kernel<<<NCTA, NTHR, SMEM_BYTES>>>(
        in[0],
        in[1], in[2], in[3], in[4],
        in[5], in[6], in[7], in[8],
        in[9], in[10], in[11], in[12],
        in[13], in[14], in[15], in[16],
        in[17], in[18],
        (float*)d_out);
}

// round 5
// speedup vs baseline: 1.2224x; 1.2224x over previous
#include <cuda_runtime.h>
#include <cstdint>

#define NCTA 128
#define NTHR 512
#define SLOT 4096                        // float2 per weight slot (256 kp x 16 cols)
#define SMEM_BYTES (4*SLOT*8 + 2*8192*4 + 1024)   // 4 slots + 2 red regions + misc

// ---------------- persistent device state (no allocations allowed) ----------
__device__ float2 g_h0[2][32768];            // layer0 h, transposed [256 kp][128 b]
__device__ float2 g_h1[2][32768];            // layer1 h
__device__ float  g_arch[256][512*128];      // decoder dh1 archive [t][k][b]
__device__ volatile unsigned g_gen;
__device__ unsigned g_cnt;

// ---------------- grid barrier (128 CTAs, all co-resident) ------------------
__device__ __forceinline__ void grid_sync() {
    __syncthreads();
    __threadfence();
    if (threadIdx.x == 0) {
        unsigned gen = g_gen;
        if (atomicAdd(&g_cnt, 1u) == NCTA - 1u) {
            atomicExch(&g_cnt, 0u);
            __threadfence();
            g_gen = gen + 1u;
        } else {
            while (g_gen == gen) __nanosleep(32);
        }
    }
    __syncthreads();
}

// ---------------- packed fp32x2 FMA (Blackwell FFMA2) -----------------------
__device__ __forceinline__ unsigned long long ffma2(unsigned long long a,
                                                    unsigned long long b,
                                                    unsigned long long c) {
    unsigned long long d;
    asm("fma.rn.f32x2 %0, %1, %2, %3;" : "=l"(d) : "l"(a), "l"(b), "l"(c));
    return d;
}
__device__ __forceinline__ float upsum(unsigned long long a) {
    return __uint_as_float((unsigned)a) + __uint_as_float((unsigned)(a >> 32));
}

// ---------------- GEMM quarter: 16 gate cols over 64 kp ---------------------
// w: smem slot [256 kp][16 cols] float2 ; h: global transposed [256 kp][128 b]
__device__ __forceinline__ void mmq(const float2* __restrict__ w,
                                    const unsigned long long* __restrict__ h,
                                    int b, int kq, unsigned long long acc[16]) {
    const unsigned long long* hp = h + kq * 8192 + b;     // 64 kp * 128 b
    const char* wb = (const char*)w + (size_t)kq * 8192;  // 64 kp * 128 B
    unsigned long long hv[4], hn[4];
#pragma unroll
    for (int j = 0; j < 4; j++) hv[j] = __ldcg(hp + j * 128);
#pragma unroll 1
    for (int k0 = 0; k0 < 64; k0 += 4) {
#pragma unroll
        for (int j = 0; j < 4; j++)
            hn[j] = __ldcg(hp + ((k0 + 4 + j) & 63) * 128);   // wrap: last-iter values unused
#pragma unroll
        for (int j = 0; j < 4; j++) {
            const ulonglong2* wr = (const ulonglong2*)(wb + (size_t)(k0 + j) * 128);
            ulonglong2 w0 = wr[0], w1 = wr[1], w2 = wr[2], w3 = wr[3];
            acc[0] = ffma2(w0.x, hv[j], acc[0]);
            acc[1] = ffma2(w0.y, hv[j], acc[1]);
            acc[2] = ffma2(w1.x, hv[j], acc[2]);
            acc[3] = ffma2(w1.y, hv[j], acc[3]);
            acc[4] = ffma2(w2.x, hv[j], acc[4]);
            acc[5] = ffma2(w2.y, hv[j], acc[5]);
            acc[6] = ffma2(w3.x, hv[j], acc[6]);
            acc[7] = ffma2(w3.y, hv[j], acc[7]);
            ulonglong2 w4 = wr[4], w5 = wr[5], w6 = wr[6], w7 = wr[7];
            acc[8]  = ffma2(w4.x, hv[j], acc[8]);
            acc[9]  = ffma2(w4.y, hv[j], acc[9]);
            acc[10] = ffma2(w5.x, hv[j], acc[10]);
            acc[11] = ffma2(w5.y, hv[j], acc[11]);
            acc[12] = ffma2(w6.x, hv[j], acc[12]);
            acc[13] = ffma2(w6.y, hv[j], acc[13]);
            acc[14] = ffma2(w7.x, hv[j], acc[14]);
            acc[15] = ffma2(w7.y, hv[j], acc[15]);
        }
#pragma unroll
        for (int j = 0; j < 4; j++) hv[j] = hn[j];
    }
}

// ---------------- k-split reduction helpers ---------------------------------
__device__ __forceinline__ void store_partial(float* __restrict__ red, int b, int kq,
                                              const unsigned long long acc[16]) {
    float* r = red + kq * 2048 + b;
#pragma unroll
    for (int i = 0; i < 16; i++) r[i * 128] = upsum(acc[i]);
}
__device__ __forceinline__ void reduce16(const float* __restrict__ red, int b, float s[16]) {
#pragma unroll
    for (int i = 0; i < 16; i++)
        s[i] = red[b + i * 128] + red[2048 + b + i * 128] +
               red[4096 + b + i * 128] + red[6144 + b + i * 128];
}

// ---------------- LSTM cell update: 4 units (kq==0 threads) -----------------
__device__ __forceinline__ void cell4(const float s[16], const float* __restrict__ bias,
                                      int b, int cta, float cr[4],
                                      float* __restrict__ hdst, float* __restrict__ arch,
                                      float* __restrict__ hout) {
#pragma unroll
    for (int u = 0; u < 4; u++) {
        float gi = s[u * 4 + 0] + bias[u * 4 + 0];
        float gf = s[u * 4 + 1] + bias[u * 4 + 1];
        float gg = s[u * 4 + 2] + bias[u * 4 + 2];
        float go = s[u * 4 + 3] + bias[u * 4 + 3];
        float iv = 1.f / (1.f + expf(-gi));
        float fv = 1.f / (1.f + expf(-gf));
        float gv = tanhf(gg);
        float ov = 1.f / (1.f + expf(-go));
        float c  = fv * cr[u] + iv * gv;
        cr[u] = c;
        float hv = ov * tanhf(c);
        if (hout) hout[u] = hv;
        int j = cta * 4 + u;
        __stcg(hdst + (j >> 1) * 256 + b * 2 + (j & 1), hv);
        if (arch) __stcg(arch + j * 128 + b, hv);
    }
}

__device__ __forceinline__ void add_xterm(float s[16], const float* __restrict__ xw,
                                          const float* __restrict__ xr) {
    float x0 = __ldg(xr),     x1 = __ldg(xr + 1), x2 = __ldg(xr + 2);
    float x3 = __ldg(xr + 3), x4 = __ldg(xr + 4), x5 = __ldg(xr + 5);
#pragma unroll
    for (int c = 0; c < 16; c++) {
        const float* wr = xw + c * 6;
        s[c] += wr[0]*x0 + wr[1]*x1 + wr[2]*x2 + wr[3]*x3 + wr[4]*x4 + wr[5]*x5;
    }
}

// Pack a (2048 x 512) weight matrix's 16 rows for this CTA into a slot.
__device__ void pack_slot(const float* __restrict__ W, float2* __restrict__ dst, int cta) {
    for (int i = threadIdx.x; i < SLOT; i += NTHR) {
        int col = i & 15, kp = i >> 4;
        int r = (col & 3) * 512 + cta * 4 + (col >> 2);
        dst[kp * 16 + col] = *(const float2*)(W + (size_t)r * 512 + kp * 2);
    }
}

// ============================================================================
__global__ void __launch_bounds__(NTHR, 1)
seq2seq_kernel(const float* __restrict__ src,
               const float* __restrict__ eWih0, const float* __restrict__ eWhh0,
               const float* __restrict__ ebih0, const float* __restrict__ ebhh0,
               const float* __restrict__ eWih1, const float* __restrict__ eWhh1,
               const float* __restrict__ ebih1, const float* __restrict__ ebhh1,
               const float* __restrict__ dWih0, const float* __restrict__ dWhh0,
               const float* __restrict__ dbih0, const float* __restrict__ dbhh0,
               const float* __restrict__ dWih1, const float* __restrict__ dWhh1,
               const float* __restrict__ dbih1, const float* __restrict__ dbhh1,
               const float* __restrict__ fcW,  const float* __restrict__ fcb,
               float* __restrict__ out) {
    extern __shared__ char smem[];
    float2* slot0 = (float2*)smem;
    float2* slot1 = slot0 + SLOT;
    float2* slot2 = slot1 + SLOT;
    float2* slot3 = slot2 + SLOT;
    float*  red0  = (float*)(slot3 + SLOT);        // 8192 floats
    float*  red1  = red0 + 8192;                   // 8192 floats
    float*  sb    = red1 + 8192;  // [0..15] b0, [16..31] b1, [32..47] bfold, [48..143] xw

    const int tid = threadIdx.x, cta = blockIdx.x;
    const int b = tid & 127, kq = tid >> 7;

    // zero both parity h buffers
    {
        float2 z = make_float2(0.f, 0.f);
        int gid = cta * NTHR + tid;
        for (int i = gid; i < 65536; i += NCTA * NTHR) {
            (&g_h0[0][0])[i] = z;
            (&g_h1[0][0])[i] = z;
        }
    }
    // pack encoder weights: slot0=Whh0, slot1=Wih1, slot2=Whh1
    pack_slot(eWhh0, slot0, cta);
    pack_slot(eWih1, slot1, cta);
    pack_slot(eWhh1, slot2, cta);
    if (tid < 16) {
        int r = (tid & 3) * 512 + cta * 4 + (tid >> 2);
        sb[tid]      = ebih0[r] + ebhh0[r];
        sb[16 + tid] = ebih1[r] + ebhh1[r];
    }
    if (tid < 96) {
        int col = tid / 6, d = tid % 6;
        int r = (col & 3) * 512 + cta * 4 + (col >> 2);
        sb[48 + tid] = eWih0[r * 6 + d];
    }
    __syncthreads();
    grid_sync();

    float cr0[4] = {0.f, 0.f, 0.f, 0.f}, cr1[4] = {0.f, 0.f, 0.f, 0.f};
    float hlast0[4] = {0.f, 0.f, 0.f, 0.f};
    int p = 0;

    // ------------- encoder: skewed, 1 barrier per interval -------------------
    // interval t computes L0 step t and L1 step t-1 (both read parity p).
    for (int t = 0; t < 256; t++) {
        unsigned long long acc[16];
#pragma unroll
        for (int i = 0; i < 16; i++) acc[i] = 0ull;
        mmq(slot0, (const unsigned long long*)g_h0[p], b, kq, acc);
        store_partial(red0, b, kq, acc);
        if (t > 0) {
#pragma unroll
            for (int i = 0; i < 16; i++) acc[i] = 0ull;
            mmq(slot1, (const unsigned long long*)g_h0[p], b, kq, acc);
            mmq(slot2, (const unsigned long long*)g_h1[p], b, kq, acc);
            store_partial(red1, b, kq, acc);
        }
        __syncthreads();
        if (kq == 0) {
            float s[16];
            reduce16(red0, b, s);
            add_xterm(s, sb + 48, src + (size_t)b * 1536 + t * 6);
            cell4(s, sb, b, cta, cr0, (float*)g_h0[p ^ 1], nullptr, hlast0);
            if (t > 0) {
                reduce16(red1, b, s);
                cell4(s, sb + 16, b, cta, cr1, (float*)g_h1[p ^ 1], nullptr, nullptr);
            }
        }
        grid_sync();
        p ^= 1;
    }
    // encoder tail: L1 step 255; also restore h0[255] into parity p^1
    {
        unsigned long long acc[16];
#pragma unroll
        for (int i = 0; i < 16; i++) acc[i] = 0ull;
        mmq(slot1, (const unsigned long long*)g_h0[p], b, kq, acc);
        mmq(slot2, (const unsigned long long*)g_h1[p], b, kq, acc);
        store_partial(red0, b, kq, acc);
        __syncthreads();
        if (kq == 0) {
            float s[16];
            reduce16(red0, b, s);
            cell4(s, sb + 16, b, cta, cr1, (float*)g_h1[p ^ 1], nullptr, nullptr);
            float* hd = (float*)g_h0[p ^ 1];
#pragma unroll
            for (int u = 0; u < 4; u++) {
                int j = cta * 4 + u;
                __stcg(hd + (j >> 1) * 256 + b * 2 + (j & 1), hlast0[u]);
            }
        }
        grid_sync();
        p ^= 1;
    }

    // ------------- repack decoder weights ------------------------------------
    pack_slot(dWhh0, slot0, cta);
    pack_slot(dWih1, slot2, cta);
    pack_slot(dWhh1, slot3, cta);
    for (int i = tid; i < SLOT; i += NTHR) {   // slot1 = Wfold = dWih0 @ fcW
        int col = i & 15, kp = i >> 4;
        int r = (col & 3) * 512 + cta * 4 + (col >> 2);
        float w0 = dWih0[r*6],   w1 = dWih0[r*6+1], w2 = dWih0[r*6+2];
        float w3 = dWih0[r*6+3], w4 = dWih0[r*6+4], w5 = dWih0[r*6+5];
        float2 v; int k = kp * 2;
        v.x = w0*fcW[k] + w1*fcW[512+k] + w2*fcW[1024+k] + w3*fcW[1536+k] + w4*fcW[2048+k] + w5*fcW[2560+k];
        k++;
        v.y = w0*fcW[k] + w1*fcW[512+k] + w2*fcW[1024+k] + w3*fcW[1536+k] + w4*fcW[2048+k] + w5*fcW[2560+k];
        slot1[kp * 16 + col] = v;
    }
    if (tid < 16) {
        int r = (tid & 3) * 512 + cta * 4 + (tid >> 2);
        sb[tid]      = dbih0[r] + dbhh0[r];
        sb[16 + tid] = dbih1[r] + dbhh1[r];
        float bf = 0.f;
        for (int d = 0; d < 6; d++) bf += dWih0[r * 6 + d] * fcb[d];
        sb[32 + tid] = bf;
    }
    if (tid < 96) {
        int col = tid / 6, d = tid % 6;
        int r = (col & 3) * 512 + cta * 4 + (col >> 2);
        sb[48 + tid] = dWih0[r * 6 + d];
    }
    __syncthreads();

    // ------------- decoder: 256 autoregressive steps, 2 barriers each --------
    for (int t = 0; t < 256; t++) {
        unsigned long long acc[16];
#pragma unroll
        for (int i = 0; i < 16; i++) acc[i] = 0ull;
        mmq(slot0, (const unsigned long long*)g_h0[p], b, kq, acc);       // Whh0 @ dh0
        if (t > 0)
            mmq(slot1, (const unsigned long long*)g_h1[p], b, kq, acc);   // Wfold @ dh1
        store_partial(red0, b, kq, acc);
        __syncthreads();
        if (kq == 0) {
            float s[16];
            reduce16(red0, b, s);
            if (t == 0) {
                add_xterm(s, sb + 48, src + (size_t)b * 1536 + 255 * 6);
            } else {
#pragma unroll
                for (int c = 0; c < 16; c++) s[c] += sb[32 + c];
            }
            cell4(s, sb, b, cta, cr0, (float*)g_h0[p ^ 1], nullptr, nullptr);
        }
        grid_sync();
#pragma unroll
        for (int i = 0; i < 16; i++) acc[i] = 0ull;
        mmq(slot2, (const unsigned long long*)g_h0[p ^ 1], b, kq, acc);   // Wih1 @ dh0_new
        mmq(slot3, (const unsigned long long*)g_h1[p],     b, kq, acc);   // Whh1 @ dh1
        store_partial(red0, b, kq, acc);
        __syncthreads();
        if (kq == 0) {
            float s[16];
            reduce16(red0, b, s);
            cell4(s, sb + 16, b, cta, cr1, (float*)g_h1[p ^ 1], g_arch[t], nullptr);
        }
        grid_sync();
        p ^= 1;
    }

    // ------------- final FC over archived dh1 states -------------------------
    __syncthreads();
    float* fw = (float*)smem;   // reuse slots: fc_W (6 x 512)
    for (int i = tid; i < 3072; i += NTHR) fw[i] = fcW[i];
    __syncthreads();
    if (tid < 256) {
        int tt = cta * 2 + (tid >> 7);
        int bb = tid & 127;
        const float* dp = g_arch[tt];
        float a0 = 0, a1 = 0, a2 = 0, a3 = 0, a4 = 0, a5 = 0;
        for (int k = 0; k < 512; k++) {
            float hv = __ldcg(dp + k * 128 + bb);
            a0 += fw[k] * hv;        a1 += fw[512 + k] * hv;  a2 += fw[1024 + k] * hv;
            a3 += fw[1536 + k] * hv; a4 += fw[2048 + k] * hv; a5 += fw[2560 + k] * hv;
        }
        float* op = out + (size_t)bb * 1536 + tt * 6;
        op[0] = a0 + __ldg(fcb);     op[1] = a1 + __ldg(fcb + 1);
        op[2] = a2 + __ldg(fcb + 2); op[3] = a3 + __ldg(fcb + 3);
        op[4] = a4 + __ldg(fcb + 4); op[5] = a5 + __ldg(fcb + 5);
    }
}

extern "C" void kernel_launch(void* const* d_in, const int* in_sizes, int n_in,
                              void* d_out, int out_size) {
    (void)in_sizes; (void)n_in; (void)out_size;
    cudaFuncSetAttribute(seq2seq_kernel,
                         cudaFuncAttributeMaxDynamicSharedMemorySize, SMEM_BYTES);
    const float* const* in = (const float* const*)d_in;
    seq2seq_kernel<<<NCTA, NTHR, SMEM_BYTES>>>(
        in[0],
        in[1], in[2], in[3], in[4],
        in[5], in[6], in[7], in[8],
        in[9], in[10], in[11], in[12],
        in[13], in[14], in[15], in[16],
        in[17], in[18],
        (float*)d_out);
}

// round 8
// speedup vs baseline: 1.2448x; 1.0183x over previous
#include <cuda_runtime.h>
#include <cstdint>

#define NCTA 128
#define NTHR 512
#define SLOT 4096                        // float2 per weight slot (256 kp x 16 cols)
#define SMEM_BYTES (4*SLOT*8 + 2*8192*4 + 1024)   // 4 slots + 2 red regions + misc

// ---------------- persistent device state (no allocations allowed) ----------
__device__ float2 g_h0[2][32768];            // layer0 h, transposed [256 kp][128 b]
__device__ float2 g_h1[2][32768];            // layer1 h
__device__ float  g_arch[256][512*128];      // decoder dh1 archive [t][k][b]
__device__ volatile unsigned g_gen;
__device__ unsigned g_cnt;

// ---------------- grid barrier (128 CTAs, all co-resident) ------------------
__device__ __forceinline__ void grid_sync() {
    __syncthreads();
    __threadfence();
    if (threadIdx.x == 0) {
        unsigned gen = g_gen;
        if (atomicAdd(&g_cnt, 1u) == NCTA - 1u) {
            atomicExch(&g_cnt, 0u);
            __threadfence();
            g_gen = gen + 1u;
        } else {
            while (g_gen == gen) __nanosleep(32);
        }
    }
    __syncthreads();
}

// ---------------- packed fp32x2 FMA (Blackwell FFMA2) -----------------------
__device__ __forceinline__ unsigned long long ffma2(unsigned long long a,
                                                    unsigned long long b,
                                                    unsigned long long c) {
    unsigned long long d;
    asm("fma.rn.f32x2 %0, %1, %2, %3;" : "=l"(d) : "l"(a), "l"(b), "l"(c));
    return d;
}
__device__ __forceinline__ float upsum(unsigned long long a) {
    return __uint_as_float((unsigned)a) + __uint_as_float((unsigned)(a >> 32));
}

// ---------------- GEMM quarter: 16 gate cols over 64 kp, 8-deep prefetch ----
// w: smem slot [256 kp][16 cols] float2 ; h: global transposed [256 kp][128 b]
__device__ __forceinline__ void mmq(const float2* __restrict__ w,
                                    const unsigned long long* __restrict__ h,
                                    int b, int kq, unsigned long long acc[16]) {
    const unsigned long long* hp = h + kq * 8192 + b;     // 64 kp * 128 b
    const char* wb = (const char*)w + (size_t)kq * 8192;  // 64 kp * 128 B
    unsigned long long hv[8];
#pragma unroll
    for (int j = 0; j < 8; j++) hv[j] = __ldcg(hp + j * 128);
#pragma unroll 1
    for (int k0 = 0; k0 < 64; k0 += 8) {
        unsigned long long cur[4];
        // ---- phase A: consume kp k0..k0+3 (hv[0..3]), refill from k0+8 ----
#pragma unroll
        for (int j = 0; j < 4; j++) cur[j] = hv[j];
#pragma unroll
        for (int j = 0; j < 4; j++) hv[j] = __ldcg(hp + ((k0 + 8 + j) & 63) * 128);
#pragma unroll
        for (int j = 0; j < 4; j++) {
            const ulonglong2* wr = (const ulonglong2*)(wb + (size_t)(k0 + j) * 128);
            ulonglong2 w0 = wr[0], w1 = wr[1], w2 = wr[2], w3 = wr[3];
            acc[0] = ffma2(w0.x, cur[j], acc[0]);
            acc[1] = ffma2(w0.y, cur[j], acc[1]);
            acc[2] = ffma2(w1.x, cur[j], acc[2]);
            acc[3] = ffma2(w1.y, cur[j], acc[3]);
            acc[4] = ffma2(w2.x, cur[j], acc[4]);
            acc[5] = ffma2(w2.y, cur[j], acc[5]);
            acc[6] = ffma2(w3.x, cur[j], acc[6]);
            acc[7] = ffma2(w3.y, cur[j], acc[7]);
            ulonglong2 w4 = wr[4], w5 = wr[5], w6 = wr[6], w7 = wr[7];
            acc[8]  = ffma2(w4.x, cur[j], acc[8]);
            acc[9]  = ffma2(w4.y, cur[j], acc[9]);
            acc[10] = ffma2(w5.x, cur[j], acc[10]);
            acc[11] = ffma2(w5.y, cur[j], acc[11]);
            acc[12] = ffma2(w6.x, cur[j], acc[12]);
            acc[13] = ffma2(w6.y, cur[j], acc[13]);
            acc[14] = ffma2(w7.x, cur[j], acc[14]);
            acc[15] = ffma2(w7.y, cur[j], acc[15]);
        }
        // ---- phase B: consume kp k0+4..k0+7 (hv[4..7]), refill from k0+12 --
#pragma unroll
        for (int j = 0; j < 4; j++) cur[j] = hv[4 + j];
#pragma unroll
        for (int j = 0; j < 4; j++) hv[4 + j] = __ldcg(hp + ((k0 + 12 + j) & 63) * 128);
#pragma unroll
        for (int j = 0; j < 4; j++) {
            const ulonglong2* wr = (const ulonglong2*)(wb + (size_t)(k0 + 4 + j) * 128);
            ulonglong2 w0 = wr[0], w1 = wr[1], w2 = wr[2], w3 = wr[3];
            acc[0] = ffma2(w0.x, cur[j], acc[0]);
            acc[1] = ffma2(w0.y, cur[j], acc[1]);
            acc[2] = ffma2(w1.x, cur[j], acc[2]);
            acc[3] = ffma2(w1.y, cur[j], acc[3]);
            acc[4] = ffma2(w2.x, cur[j], acc[4]);
            acc[5] = ffma2(w2.y, cur[j], acc[5]);
            acc[6] = ffma2(w3.x, cur[j], acc[6]);
            acc[7] = ffma2(w3.y, cur[j], acc[7]);
            ulonglong2 w4 = wr[4], w5 = wr[5], w6 = wr[6], w7 = wr[7];
            acc[8]  = ffma2(w4.x, cur[j], acc[8]);
            acc[9]  = ffma2(w4.y, cur[j], acc[9]);
            acc[10] = ffma2(w5.x, cur[j], acc[10]);
            acc[11] = ffma2(w5.y, cur[j], acc[11]);
            acc[12] = ffma2(w6.x, cur[j], acc[12]);
            acc[13] = ffma2(w6.y, cur[j], acc[13]);
            acc[14] = ffma2(w7.x, cur[j], acc[14]);
            acc[15] = ffma2(w7.y, cur[j], acc[15]);
        }
    }
}

// ---------------- k-split reduction + per-unit cell (all 512 threads) -------
__device__ __forceinline__ void store_partial(float* __restrict__ red, int b, int kq,
                                              const unsigned long long acc[16]) {
    float* r = red + kq * 2048 + b;
#pragma unroll
    for (int i = 0; i < 16; i++) r[i * 128] = upsum(acc[i]);
}
// thread (b,kq) reduces the 4 gate columns of unit kq
__device__ __forceinline__ void reduce4(const float* __restrict__ red, int b, int kq,
                                        float s[4]) {
#pragma unroll
    for (int g = 0; g < 4; g++) {
        int c = (kq * 4 + g) * 128 + b;
        s[g] = red[c] + red[2048 + c] + red[4096 + c] + red[6144 + c];
    }
}
// one LSTM cell for unit kq at batch b
__device__ __forceinline__ float cell1(const float s[4], const float* __restrict__ bias,
                                       int b, int cta, int kq, float& cr,
                                       float* __restrict__ hdst, float* __restrict__ arch) {
    int col = kq * 4;
    float gi = s[0] + bias[col + 0];
    float gf = s[1] + bias[col + 1];
    float gg = s[2] + bias[col + 2];
    float go = s[3] + bias[col + 3];
    float iv = 1.f / (1.f + expf(-gi));
    float fv = 1.f / (1.f + expf(-gf));
    float gv = tanhf(gg);
    float ov = 1.f / (1.f + expf(-go));
    float c  = fv * cr + iv * gv;
    cr = c;
    float hv = ov * tanhf(c);
    int j = cta * 4 + kq;
    __stcg(hdst + (j >> 1) * 256 + b * 2 + (j & 1), hv);
    if (arch) __stcg(arch + j * 128 + b, hv);
    return hv;
}

__device__ __forceinline__ void add_xterm4(float s[4], const float* __restrict__ xw,
                                           int kq, const float* __restrict__ xr) {
    float x0 = __ldg(xr),     x1 = __ldg(xr + 1), x2 = __ldg(xr + 2);
    float x3 = __ldg(xr + 3), x4 = __ldg(xr + 4), x5 = __ldg(xr + 5);
#pragma unroll
    for (int g = 0; g < 4; g++) {
        const float* wr = xw + (kq * 4 + g) * 6;
        s[g] += wr[0]*x0 + wr[1]*x1 + wr[2]*x2 + wr[3]*x3 + wr[4]*x4 + wr[5]*x5;
    }
}

// Pack a (2048 x 512) weight matrix's 16 rows for this CTA into a slot.
__device__ void pack_slot(const float* __restrict__ W, float2* __restrict__ dst, int cta) {
    for (int i = threadIdx.x; i < SLOT; i += NTHR) {
        int col = i & 15, kp = i >> 4;
        int r = (col & 3) * 512 + cta * 4 + (col >> 2);
        dst[kp * 16 + col] = *(const float2*)(W + (size_t)r * 512 + kp * 2);
    }
}

// ============================================================================
__global__ void __launch_bounds__(NTHR, 1)
seq2seq_kernel(const float* __restrict__ src,
               const float* __restrict__ eWih0, const float* __restrict__ eWhh0,
               const float* __restrict__ ebih0, const float* __restrict__ ebhh0,
               const float* __restrict__ eWih1, const float* __restrict__ eWhh1,
               const float* __restrict__ ebih1, const float* __restrict__ ebhh1,
               const float* __restrict__ dWih0, const float* __restrict__ dWhh0,
               const float* __restrict__ dbih0, const float* __restrict__ dbhh0,
               const float* __restrict__ dWih1, const float* __restrict__ dWhh1,
               const float* __restrict__ dbih1, const float* __restrict__ dbhh1,
               const float* __restrict__ fcW,  const float* __restrict__ fcb,
               float* __restrict__ out) {
    extern __shared__ char smem[];
    float2* slot0 = (float2*)smem;
    float2* slot1 = slot0 + SLOT;
    float2* slot2 = slot1 + SLOT;
    float2* slot3 = slot2 + SLOT;
    float*  red0  = (float*)(slot3 + SLOT);        // 8192 floats
    float*  red1  = red0 + 8192;                   // 8192 floats
    float*  sb    = red1 + 8192;  // [0..15] b0, [16..31] b1, [32..47] bfold, [48..143] xw

    const int tid = threadIdx.x, cta = blockIdx.x;
    const int b = tid & 127, kq = tid >> 7;

    // zero both parity h buffers
    {
        float2 z = make_float2(0.f, 0.f);
        int gid = cta * NTHR + tid;
        for (int i = gid; i < 65536; i += NCTA * NTHR) {
            (&g_h0[0][0])[i] = z;
            (&g_h1[0][0])[i] = z;
        }
    }
    // pack encoder weights: slot0=Whh0, slot1=Wih1, slot2=Whh1
    pack_slot(eWhh0, slot0, cta);
    pack_slot(eWih1, slot1, cta);
    pack_slot(eWhh1, slot2, cta);
    if (tid < 16) {
        int r = (tid & 3) * 512 + cta * 4 + (tid >> 2);
        sb[tid]      = ebih0[r] + ebhh0[r];
        sb[16 + tid] = ebih1[r] + ebhh1[r];
    }
    if (tid < 96) {
        int col = tid / 6, d = tid % 6;
        int r = (col & 3) * 512 + cta * 4 + (col >> 2);
        sb[48 + tid] = eWih0[r * 6 + d];
    }
    __syncthreads();
    grid_sync();

    float cr0 = 0.f, cr1 = 0.f, hlast0 = 0.f;
    int p = 0;

    // ------------- encoder: skewed, 1 barrier per interval -------------------
    // interval t computes L0 step t and L1 step t-1 (both read parity p).
    for (int t = 0; t < 256; t++) {
        unsigned long long acc[16];
#pragma unroll
        for (int i = 0; i < 16; i++) acc[i] = 0ull;
        mmq(slot0, (const unsigned long long*)g_h0[p], b, kq, acc);
        store_partial(red0, b, kq, acc);
        if (t > 0) {
#pragma unroll
            for (int i = 0; i < 16; i++) acc[i] = 0ull;
            mmq(slot1, (const unsigned long long*)g_h0[p], b, kq, acc);
            mmq(slot2, (const unsigned long long*)g_h1[p], b, kq, acc);
            store_partial(red1, b, kq, acc);
        }
        __syncthreads();
        {
            float s[4];
            reduce4(red0, b, kq, s);
            add_xterm4(s, sb + 48, kq, src + (size_t)b * 1536 + t * 6);
            hlast0 = cell1(s, sb, b, cta, kq, cr0, (float*)g_h0[p ^ 1], nullptr);
            if (t > 0) {
                reduce4(red1, b, kq, s);
                cell1(s, sb + 16, b, cta, kq, cr1, (float*)g_h1[p ^ 1], nullptr);
            }
        }
        grid_sync();
        p ^= 1;
    }
    // encoder tail: L1 step 255; restore h0[255] into parity p^1
    {
        unsigned long long acc[16];
#pragma unroll
        for (int i = 0; i < 16; i++) acc[i] = 0ull;
        mmq(slot1, (const unsigned long long*)g_h0[p], b, kq, acc);
        mmq(slot2, (const unsigned long long*)g_h1[p], b, kq, acc);
        store_partial(red0, b, kq, acc);
        __syncthreads();
        {
            float s[4];
            reduce4(red0, b, kq, s);
            cell1(s, sb + 16, b, cta, kq, cr1, (float*)g_h1[p ^ 1], nullptr);
            float* hd = (float*)g_h0[p ^ 1];
            int j = cta * 4 + kq;
            __stcg(hd + (j >> 1) * 256 + b * 2 + (j & 1), hlast0);
        }
        grid_sync();
        p ^= 1;
    }

    // ------------- repack decoder weights ------------------------------------
    pack_slot(dWhh0, slot0, cta);
    pack_slot(dWih1, slot2, cta);
    pack_slot(dWhh1, slot3, cta);
    for (int i = tid; i < SLOT; i += NTHR) {   // slot1 = Wfold = dWih0 @ fcW
        int col = i & 15, kp = i >> 4;
        int r = (col & 3) * 512 + cta * 4 + (col >> 2);
        float w0 = dWih0[r*6],   w1 = dWih0[r*6+1], w2 = dWih0[r*6+2];
        float w3 = dWih0[r*6+3], w4 = dWih0[r*6+4], w5 = dWih0[r*6+5];
        float2 v; int k = kp * 2;
        v.x = w0*fcW[k] + w1*fcW[512+k] + w2*fcW[1024+k] + w3*fcW[1536+k] + w4*fcW[2048+k] + w5*fcW[2560+k];
        k++;
        v.y = w0*fcW[k] + w1*fcW[512+k] + w2*fcW[1024+k] + w3*fcW[1536+k] + w4*fcW[2048+k] + w5*fcW[2560+k];
        slot1[kp * 16 + col] = v;
    }
    if (tid < 16) {
        int r = (tid & 3) * 512 + cta * 4 + (tid >> 2);
        sb[tid]      = dbih0[r] + dbhh0[r];
        sb[16 + tid] = dbih1[r] + dbhh1[r];
        float bf = 0.f;
        for (int d = 0; d < 6; d++) bf += dWih0[r * 6 + d] * fcb[d];
        sb[32 + tid] = bf;
    }
    if (tid < 96) {
        int col = tid / 6, d = tid % 6;
        int r = (col & 3) * 512 + cta * 4 + (col >> 2);
        sb[48 + tid] = dWih0[r * 6 + d];
    }
    __syncthreads();

    // ------------- decoder: 256 autoregressive steps, 2 barriers each --------
    for (int t = 0; t < 256; t++) {
        unsigned long long acc[16];
#pragma unroll
        for (int i = 0; i < 16; i++) acc[i] = 0ull;
        mmq(slot0, (const unsigned long long*)g_h0[p], b, kq, acc);       // Whh0 @ dh0
        if (t > 0)
            mmq(slot1, (const unsigned long long*)g_h1[p], b, kq, acc);   // Wfold @ dh1
        store_partial(red0, b, kq, acc);
        __syncthreads();
        {
            float s[4];
            reduce4(red0, b, kq, s);
            if (t == 0) {
                add_xterm4(s, sb + 48, kq, src + (size_t)b * 1536 + 255 * 6);
            } else {
#pragma unroll
                for (int g = 0; g < 4; g++) s[g] += sb[32 + kq * 4 + g];
            }
            cell1(s, sb, b, cta, kq, cr0, (float*)g_h0[p ^ 1], nullptr);
        }
        grid_sync();
#pragma unroll
        for (int i = 0; i < 16; i++) acc[i] = 0ull;
        mmq(slot2, (const unsigned long long*)g_h0[p ^ 1], b, kq, acc);   // Wih1 @ dh0_new
        mmq(slot3, (const unsigned long long*)g_h1[p],     b, kq, acc);   // Whh1 @ dh1
        store_partial(red0, b, kq, acc);
        __syncthreads();
        {
            float s[4];
            reduce4(red0, b, kq, s);
            cell1(s, sb + 16, b, cta, kq, cr1, (float*)g_h1[p ^ 1], g_arch[t]);
        }
        grid_sync();
        p ^= 1;
    }

    // ------------- final FC over archived dh1 states -------------------------
    __syncthreads();
    float* fw = (float*)smem;   // reuse slots: fc_W (6 x 512)
    for (int i = tid; i < 3072; i += NTHR) fw[i] = fcW[i];
    __syncthreads();
    if (tid < 256) {
        int tt = cta * 2 + (tid >> 7);
        int bb = tid & 127;
        const float* dp = g_arch[tt];
        float a0 = 0, a1 = 0, a2 = 0, a3 = 0, a4 = 0, a5 = 0;
        for (int k = 0; k < 512; k++) {
            float hv = __ldcg(dp + k * 128 + bb);
            a0 += fw[k] * hv;        a1 += fw[512 + k] * hv;  a2 += fw[1024 + k] * hv;
            a3 += fw[1536 + k] * hv; a4 += fw[2048 + k] * hv; a5 += fw[2560 + k] * hv;
        }
        float* op = out + (size_t)bb * 1536 + tt * 6;
        op[0] = a0 + __ldg(fcb);     op[1] = a1 + __ldg(fcb + 1);
        op[2] = a2 + __ldg(fcb + 2); op[3] = a3 + __ldg(fcb + 3);
        op[4] = a4 + __ldg(fcb + 4); op[5] = a5 + __ldg(fcb + 5);
    }
}

extern "C" void kernel_launch(void* const* d_in, const int* in_sizes, int n_in,
                              void* d_out, int out_size) {
    (void)in_sizes; (void)n_in; (void)out_size;
    cudaFuncSetAttribute(seq2seq_kernel,
                         cudaFuncAttributeMaxDynamicSharedMemorySize, SMEM_BYTES);
    const float* const* in = (const float* const*)d_in;
    seq2seq_kernel<<<NCTA, NTHR, SMEM_BYTES>>>(
        in[0],
        in[1], in[2], in[3], in[4],
        in[5], in[6], in[7], in[8],
        in[9], in[10], in[11], in[12],
        in[13], in[14], in[15], in[16],
        in[17], in[18],
        (float*)d_out);
}